// round 3
// baseline (speedup 1.0000x reference)
#include <cuda_runtime.h>
#include <cuda_fp16.h>

#define N_NODES 100000
#define N_EDGES 3200000
#define D       64
#define NH      128

typedef unsigned long long u64;

// Scratch (allocation-free rule: __device__ globals)
__device__ __half g_Ah[(size_t)N_NODES * NH];   // 25.6 MB: W1[:, :64] @ z[n] + b1   (fp16)
__device__ __half g_Bh[(size_t)N_NODES * NH];   // 25.6 MB: W1[:, 64:] @ z[n]        (fp16)
__device__ float  g_WT2[64 * 256];              // k-pair-interleaved fused weights

// ---------------------------------------------------------------------------
// Kernel 0: build g_WT2 in FFMA2-friendly layout.
//   idx = ((kp*4 + u)*32 + jg)*4 + c
//   k = kp*2 + (c&1),  j = jg*8 + u*2 + (c>>1)
//   value = (j < 128) ? W1[j][k] : W1[j-128][64+k]
// So each float4 = { W[k][j0], W[k+1][j0], W[k][j1], W[k+1][j1] } with
// j0 = jg*8+2u, j1 = j0+1  -> two b64 packed (k,k+1) operands per LDS.128.
// ---------------------------------------------------------------------------
__global__ void build_wt(const float* __restrict__ W1) {
    int idx = blockIdx.x * 256 + threadIdx.x;   // 0..16383
    int c  = idx & 3;
    int jg = (idx >> 2) & 31;
    int u  = (idx >> 7) & 3;
    int kp = idx >> 9;                          // 0..31
    int k  = kp * 2 + (c & 1);
    int j  = jg * 8 + u * 2 + (c >> 1);
    float v = (j < 128) ? W1[j * NH + k] : W1[(j - 128) * NH + 64 + k];
    g_WT2[idx] = v;
}

__device__ __forceinline__ void ffma2(u64& d, u64 a, u64 b) {
    asm("fma.rn.f32x2 %0, %1, %2, %0;" : "+l"(d) : "l"(a), "l"(b));
}

// ---------------------------------------------------------------------------
// Kernel 1: node GEMM via packed fp32x2 FFMA (k-parity packed lanes).
// Block: 32 nodes x 256 outputs, 256 threads.
// Thread (jg = tid&31, ng = tid>>5): 4 nodes (ng*4..+3) x 8 cols (jg*8..+7).
// acc[n][u2] : b64 pair accumulating (k even, k odd) partial sums for one col.
// Inner loop per k-pair: 4x LDS.64 (z, broadcast) + 4x LDS.128 (w, conflict-
// free 512B/warp) + 32x FFMA2. Epilogue: lo+hi, +b1 (A half), fp16 pack.
// ---------------------------------------------------------------------------
__global__ void node_gemm(const float* __restrict__ z, const float* __restrict__ b1) {
    __shared__ float sZ[32 * 64];    // 8 KB
    __shared__ float sW[8192];       // 32 KB (one 32-k chunk)

    const int tid      = threadIdx.x;
    const int nodeBase = blockIdx.x * 32;

    // load z tile (32 nodes x 64 feats), coalesced
    #pragma unroll
    for (int t = 0; t < 8; t++)
        sZ[tid + t * 256] = z[(size_t)nodeBase * D + tid + t * 256];

    const int jg = tid & 31;     // col group: cols jg*8 .. jg*8+7
    const int ng = tid >> 5;     // node group: nodes ng*4 .. ng*4+3

    u64 acc[4][8];
    #pragma unroll
    for (int n = 0; n < 4; n++)
        #pragma unroll
        for (int p = 0; p < 8; p++) acc[n][p] = 0ull;

    const ulonglong2* sWu2 = (const ulonglong2*)sW;

    #pragma unroll
    for (int kc = 0; kc < 2; kc++) {
        __syncthreads();   // iter0: orders sZ fill; iter1: protects sW reuse
        #pragma unroll
        for (int t = 0; t < 32; t++)
            sW[tid + t * 256] = g_WT2[kc * 8192 + tid + t * 256];
        __syncthreads();

        #pragma unroll
        for (int kp = 0; kp < 16; kp++) {
            u64 zz[4];
            #pragma unroll
            for (int n = 0; n < 4; n++)
                zz[n] = *(const u64*)&sZ[(ng * 4 + n) * 64 + kc * 32 + kp * 2];

            #pragma unroll
            for (int u = 0; u < 4; u++) {
                ulonglong2 wv = sWu2[(kp * 4 + u) * 32 + jg];
                #pragma unroll
                for (int n = 0; n < 4; n++) {
                    ffma2(acc[n][u * 2],     wv.x, zz[n]);
                    ffma2(acc[n][u * 2 + 1], wv.y, zz[n]);
                }
            }
        }
    }

    // epilogue: horizontal add (k-even + k-odd), +b1 for A half, fp16 pack
    float bv[8];
    if (jg < 16) {
        float4 ba = ((const float4*)b1)[jg * 2];
        float4 bb = ((const float4*)b1)[jg * 2 + 1];
        bv[0] = ba.x; bv[1] = ba.y; bv[2] = ba.z; bv[3] = ba.w;
        bv[4] = bb.x; bv[5] = bb.y; bv[6] = bb.z; bv[7] = bb.w;
    } else {
        #pragma unroll
        for (int t = 0; t < 8; t++) bv[t] = 0.f;
    }

    #pragma unroll
    for (int n = 0; n < 4; n++) {
        int node = nodeBase + ng * 4 + n;
        float o[8];
        #pragma unroll
        for (int p = 0; p < 8; p++) {
            float2 f = *(float2*)&acc[n][p];
            o[p] = f.x + f.y + bv[p];
        }
        __half2 h0 = __floats2half2_rn(o[0], o[1]);
        __half2 h1 = __floats2half2_rn(o[2], o[3]);
        __half2 h2 = __floats2half2_rn(o[4], o[5]);
        __half2 h3 = __floats2half2_rn(o[6], o[7]);
        uint4 pk;
        pk.x = *(const unsigned int*)&h0;
        pk.y = *(const unsigned int*)&h1;
        pk.z = *(const unsigned int*)&h2;
        pk.w = *(const unsigned int*)&h3;
        if (jg < 16)
            ((uint4*)(g_Ah + (size_t)node * NH))[jg] = pk;
        else
            ((uint4*)(g_Bh + (size_t)node * NH))[jg - 16] = pk;
    }
}

// ---------------------------------------------------------------------------
// Kernel 2: edge pass. out[e] = W2 . relu(A[row[e]] + B[col[e]]) + b2
// fp16 tables, fp32 math. 8 lanes per edge, 4 edges per warp. Each lane:
// 2x LDG.128 from A-row + 2x from B-row. shfl reduce across 8 lanes.
// L2-bandwidth bound (~1.68 GB through LTS).
// ---------------------------------------------------------------------------
__global__ void edge_kernel(const int* __restrict__ row, const int* __restrict__ col,
                            const float* __restrict__ W2, const float* __restrict__ b2,
                            float* __restrict__ out) {
    const int lane = threadIdx.x & 31;
    const int warp = threadIdx.x >> 5;
    const int g    = lane >> 3;   // edge slot within warp (0..3)
    const int i    = lane & 7;    // lane within edge (0..7)

    const long e = (long)blockIdx.x * 32 + warp * 4 + g;
    if (e >= N_EDGES) return;

    // hoisted W2 for this lane: groups i and 8+i of 8 floats each
    float w[2][8];
    #pragma unroll
    for (int q = 0; q < 2; q++)
        #pragma unroll
        for (int t = 0; t < 8; t++)
            w[q][t] = W2[(q * 8 + i) * 8 + t];

    const int r = row[e];
    const int c = col[e];
    const uint4* __restrict__ Ar = (const uint4*)(g_Ah + (size_t)r * NH);
    const uint4* __restrict__ Bc = (const uint4*)(g_Bh + (size_t)c * NH);

    float s = 0.f;
    #pragma unroll
    for (int q = 0; q < 2; q++) {
        uint4 av = Ar[q * 8 + i];   // 8 halves
        uint4 bv = Bc[q * 8 + i];
        const __half2* ah = (const __half2*)&av;
        const __half2* bh = (const __half2*)&bv;
        #pragma unroll
        for (int t = 0; t < 4; t++) {
            float2 af = __half22float2(ah[t]);
            float2 bf = __half22float2(bh[t]);
            s += w[q][2 * t]     * fmaxf(af.x + bf.x, 0.f);
            s += w[q][2 * t + 1] * fmaxf(af.y + bf.y, 0.f);
        }
    }

    // reduce across the 8 lanes of this edge
    s += __shfl_xor_sync(0xffffffffu, s, 1);
    s += __shfl_xor_sync(0xffffffffu, s, 2);
    s += __shfl_xor_sync(0xffffffffu, s, 4);

    if (i == 0) out[e] = s + b2[0];
}

// ---------------------------------------------------------------------------
extern "C" void kernel_launch(void* const* d_in, const int* in_sizes, int n_in,
                              void* d_out, int out_size) {
    const float* z   = (const float*)d_in[0];
    const int*   row = (const int*)  d_in[1];
    const int*   col = (const int*)  d_in[2];
    const float* W1  = (const float*)d_in[3];
    const float* b1  = (const float*)d_in[4];
    const float* W2  = (const float*)d_in[5];
    const float* b2  = (const float*)d_in[6];
    float* out = (float*)d_out;

    build_wt<<<64, 256>>>(W1);
    node_gemm<<<N_NODES / 32, 256>>>(z, b1);                    // 3125 blocks
    edge_kernel<<<N_EDGES / 32, 256>>>(row, col, W2, b2, out);  // 100000 blocks
}

// round 4
// speedup vs baseline: 1.2804x; 1.2804x over previous
#include <cuda_runtime.h>
#include <cuda_fp16.h>

#define N_NODES 100000
#define N_EDGES 3200000
#define D       64
#define NH      128

// Scratch (allocation-free rule: __device__ globals)
__device__ __half g_Ah[(size_t)N_NODES * NH];   // 25.6 MB: W1[:, :64] @ z[n] + b1   (fp16)
__device__ __half g_Bh[(size_t)N_NODES * NH];   // 25.6 MB: W1[:, 64:] @ z[n]        (fp16)
__device__ float  g_WT[64 * 256];               // fused transposed weights

// ---------------------------------------------------------------------------
// Kernel 0: build WT[k][jj]:  jj<128 -> W1[jj][k]   (A half, k = 0..63)
//                             jj>=128 -> W1[jj-128][64+k] (B half)
// ---------------------------------------------------------------------------
__global__ void build_wt(const float* __restrict__ W1) {
    int k  = blockIdx.x;    // 0..63
    int jj = threadIdx.x;   // 0..255
    float v = (jj < 128) ? W1[jj * NH + k] : W1[(jj - 128) * NH + 64 + k];
    g_WT[k * 256 + jj] = v;
}

// ---------------------------------------------------------------------------
// Kernel 1: node GEMM (R2 version — measured best).  Each block: 32 nodes x
// 256 outputs (A:128 | B:128). 256 threads, each owns 8 nodes x 1 float4.
// z read from smem via float4 broadcast. Results stored as fp16.
// ---------------------------------------------------------------------------
__global__ void node_gemm(const float* __restrict__ z, const float* __restrict__ b1) {
    __shared__ float sZ[32 * 64];    // 8 KB
    __shared__ float sW[32 * 256];   // 32 KB

    const int tid      = threadIdx.x;
    const int nodeBase = blockIdx.x * 32;

    #pragma unroll
    for (int t = 0; t < 8; t++)
        sZ[tid + t * 256] = z[(size_t)nodeBase * D + tid + t * 256];

    const int j4 = tid & 63;          // float4 column group 0..63 (256 outputs)
    const int nb = (tid >> 6) * 8;    // node sub-base 0,8,16,24

    const float4* sZ4 = (const float4*)sZ;   // [32 nodes][16 float4]
    const float4* sW4 = (const float4*)sW;   // [32 k][64 float4]

    float4 acc[8];
    #pragma unroll
    for (int n = 0; n < 8; n++) acc[n] = make_float4(0.f, 0.f, 0.f, 0.f);

    #pragma unroll
    for (int kc = 0; kc < 2; kc++) {
        __syncthreads();
        #pragma unroll
        for (int t = 0; t < 32; t++)
            sW[tid + t * 256] = g_WT[kc * 32 * 256 + tid + t * 256];
        __syncthreads();

        #pragma unroll
        for (int kk4 = 0; kk4 < 8; kk4++) {
            float4 zv[8];
            #pragma unroll
            for (int n = 0; n < 8; n++)
                zv[n] = sZ4[(nb + n) * 16 + kc * 8 + kk4];

            #pragma unroll
            for (int u = 0; u < 4; u++) {
                float4 w = sW4[(kk4 * 4 + u) * 64 + j4];
                #pragma unroll
                for (int n = 0; n < 8; n++) {
                    float zs = (u == 0) ? zv[n].x : (u == 1) ? zv[n].y
                             : (u == 2) ? zv[n].z : zv[n].w;
                    acc[n].x += w.x * zs;
                    acc[n].y += w.y * zs;
                    acc[n].z += w.z * zs;
                    acc[n].w += w.w * zs;
                }
            }
        }
    }

    if (j4 < 32) {  // A half: add b1
        float4 bv = ((const float4*)b1)[j4];
        #pragma unroll
        for (int n = 0; n < 8; n++) {
            int node = nodeBase + nb + n;
            float4 o = acc[n];
            o.x += bv.x; o.y += bv.y; o.z += bv.z; o.w += bv.w;
            __half2 h0 = __floats2half2_rn(o.x, o.y);
            __half2 h1 = __floats2half2_rn(o.z, o.w);
            uint2 pk;
            pk.x = *(const unsigned int*)&h0;
            pk.y = *(const unsigned int*)&h1;
            ((uint2*)(g_Ah + (size_t)node * NH))[j4] = pk;
        }
    } else {        // B half
        #pragma unroll
        for (int n = 0; n < 8; n++) {
            int node = nodeBase + nb + n;
            float4 o = acc[n];
            __half2 h0 = __floats2half2_rn(o.x, o.y);
            __half2 h1 = __floats2half2_rn(o.z, o.w);
            uint2 pk;
            pk.x = *(const unsigned int*)&h0;
            pk.y = *(const unsigned int*)&h1;
            ((uint2*)(g_Bh + (size_t)node * NH))[j4 - 32] = pk;
        }
    }
}

// ---------------------------------------------------------------------------
// Kernel 2: edge pass, persistent grid-stride. out[e] = W2.relu(A[r]+B[c])+b2
// 8 lanes per edge, 4 edge-slots per warp, unroll-by-2 (8 edges per warp-iter).
// W2 hoisted ONCE per thread (4x LDG.128). Per 8 edges: 4 idx LDG + 32 table
// LDG.128 = 4.5 LDG/edge  ->  below LSU issue floor; L2-BW bound (~1.64 GB).
// fp16 tables, fp32 math.
// ---------------------------------------------------------------------------
#define EDGE_BLOCKS 1184

__global__ void edge_kernel(const int* __restrict__ row, const int* __restrict__ col,
                            const float* __restrict__ W2, const float* __restrict__ b2,
                            float* __restrict__ out) {
    const int lane = threadIdx.x & 31;
    const int warp = threadIdx.x >> 5;
    const int g    = lane >> 3;   // edge slot within warp (0..3)
    const int i    = lane & 7;    // lane within edge (0..7)

    // W2 hoist: lane i covers cols {8i..8i+7} and {64+8i..64+8i+7}
    const float4* W24 = (const float4*)W2;
    float4 w4[4];
    #pragma unroll
    for (int q = 0; q < 2; q++)
        #pragma unroll
        for (int h = 0; h < 2; h++)
            w4[q * 2 + h] = W24[(q * 8 + i) * 2 + h];
    const float bias = b2[0];

    const int warpGlobal = blockIdx.x * 8 + warp;
    const int nWarps     = EDGE_BLOCKS * 8;        // 9472

    // N_EDGES divisible by 8: both sub-iterations always valid
    for (long e0 = (long)warpGlobal * 8; e0 < N_EDGES; e0 += (long)nWarps * 8) {
        const long eA = e0 + g;
        const long eB = e0 + 4 + g;

        const int rA = row[eA], cA = col[eA];
        const int rB = row[eB], cB = col[eB];

        const uint4* __restrict__ ArA = (const uint4*)(g_Ah + (size_t)rA * NH);
        const uint4* __restrict__ BcA = (const uint4*)(g_Bh + (size_t)cA * NH);
        const uint4* __restrict__ ArB = (const uint4*)(g_Ah + (size_t)rB * NH);
        const uint4* __restrict__ BcB = (const uint4*)(g_Bh + (size_t)cB * NH);

        uint4 avA[2], bvA[2], avB[2], bvB[2];
        #pragma unroll
        for (int q = 0; q < 2; q++) {
            avA[q] = ArA[q * 8 + i];  bvA[q] = BcA[q * 8 + i];
            avB[q] = ArB[q * 8 + i];  bvB[q] = BcB[q * 8 + i];
        }

        float sA = 0.f, sB = 0.f;
        #pragma unroll
        for (int q = 0; q < 2; q++) {
            const __half2* ahA = (const __half2*)&avA[q];
            const __half2* bhA = (const __half2*)&bvA[q];
            const __half2* ahB = (const __half2*)&avB[q];
            const __half2* bhB = (const __half2*)&bvB[q];
            const float* wq = (const float*)&w4[q * 2];
            #pragma unroll
            for (int t = 0; t < 4; t++) {
                float2 afA = __half22float2(ahA[t]);
                float2 bfA = __half22float2(bhA[t]);
                sA += wq[2 * t]     * fmaxf(afA.x + bfA.x, 0.f);
                sA += wq[2 * t + 1] * fmaxf(afA.y + bfA.y, 0.f);
                float2 afB = __half22float2(ahB[t]);
                float2 bfB = __half22float2(bhB[t]);
                sB += wq[2 * t]     * fmaxf(afB.x + bfB.x, 0.f);
                sB += wq[2 * t + 1] * fmaxf(afB.y + bfB.y, 0.f);
            }
        }

        // reduce across the 8 lanes of each edge
        sA += __shfl_xor_sync(0xffffffffu, sA, 1);
        sA += __shfl_xor_sync(0xffffffffu, sA, 2);
        sA += __shfl_xor_sync(0xffffffffu, sA, 4);
        sB += __shfl_xor_sync(0xffffffffu, sB, 1);
        sB += __shfl_xor_sync(0xffffffffu, sB, 2);
        sB += __shfl_xor_sync(0xffffffffu, sB, 4);

        if (i == 0) {
            out[eA] = sA + bias;
            out[eB] = sB + bias;
        }
    }
}

// ---------------------------------------------------------------------------
extern "C" void kernel_launch(void* const* d_in, const int* in_sizes, int n_in,
                              void* d_out, int out_size) {
    const float* z   = (const float*)d_in[0];
    const int*   row = (const int*)  d_in[1];
    const int*   col = (const int*)  d_in[2];
    const float* W1  = (const float*)d_in[3];
    const float* b1  = (const float*)d_in[4];
    const float* W2  = (const float*)d_in[5];
    const float* b2  = (const float*)d_in[6];
    float* out = (float*)d_out;

    build_wt<<<64, 256>>>(W1);
    node_gemm<<<N_NODES / 32, 256>>>(z, b1);                      // 3125 blocks
    edge_kernel<<<EDGE_BLOCKS, 256>>>(row, col, W2, b2, out);     // persistent
}

// round 6
// speedup vs baseline: 1.4613x; 1.1412x over previous
#include <cuda_runtime.h>
#include <cuda_fp16.h>
#include <cstdint>

#define N_NODES 100000
#define N_EDGES 3200000
#define D       64
#define NH      128

// ---------------------------------------------------------------------------
// Scratch (allocation-free rule: __device__ globals)
// ---------------------------------------------------------------------------
__device__ __half g_Ah[(size_t)N_NODES * NH];   // 25.6 MB: W1[:, :64] @ z + b1  (fp16)
__device__ __half g_Bh[(size_t)N_NODES * NH];   // 25.6 MB: W1[:, 64:] @ z       (fp16)
// Fused weight table [n=256][k=64] fp16, hi/lo split, XOR-swizzled:
//   byte(n,k) = n*128 + ((2k) ^ ((n&7)<<4))
__device__ unsigned char g_Wh[256 * 128];
__device__ unsigned char g_Wl[256 * 128];

// ---------------------------------------------------------------------------
// smem layout for node_mma (bytes)
// ---------------------------------------------------------------------------
#define SM_B1   0            // 512 B
#define SM_ZH   512          // 16 KB   zh [128 rows][128 B]
#define SM_ZL   16896        // 16 KB   zl
#define SM_WH   33280        // 32 KB   Wh [256 rows][128 B]
#define SM_WL   66048        // 32 KB   Wl
#define SM_TOT  98816

// ---------------------------------------------------------------------------
// Kernel 0: build split fp16 weight tables (swizzled).
//   n < 128 : W[n][k] = W1[n][k]          (A half)
//   n >=128 : W[n][k] = W1[n-128][64+k]   (B half)
// ---------------------------------------------------------------------------
__global__ void build_wt(const float* __restrict__ W1) {
    int idx = blockIdx.x * 256 + threadIdx.x;   // 0..16383
    int n = idx >> 6;
    int k = idx & 63;
    float w = (n < 128) ? W1[n * NH + k] : W1[(n - 128) * NH + 64 + k];
    __half wh = __float2half_rn(w);
    __half wl = __float2half_rn(w - __half2float(wh));
    uint32_t off = (uint32_t)(n * 128 + ((k * 2) ^ ((n & 7) << 4)));
    *(__half*)(g_Wh + off) = wh;
    *(__half*)(g_Wl + off) = wl;
}

// ---------------------------------------------------------------------------
// m16n8k16 fp16 MMA, fp32 accumulators (sm_80+ PTX, no 'a'-gated features)
// ---------------------------------------------------------------------------
__device__ __forceinline__ void mma16816(float* c, const uint32_t* a,
                                         uint32_t b0, uint32_t b1) {
    asm volatile(
        "mma.sync.aligned.m16n8k16.row.col.f32.f16.f16.f32 "
        "{%0,%1,%2,%3}, {%4,%5,%6,%7}, {%8,%9}, {%0,%1,%2,%3};"
        : "+f"(c[0]), "+f"(c[1]), "+f"(c[2]), "+f"(c[3])
        : "r"(a[0]), "r"(a[1]), "r"(a[2]), "r"(a[3]), "r"(b0), "r"(b1));
}

// ---------------------------------------------------------------------------
// Kernel 1: node GEMM on tensor cores, fp32-exact via fp16 split.
// Per CTA: D[128 nodes x 256 cols] = z[128x64] @ W[64x256]
//        = zh@Wh + zh@Wl + zl@Wh   (fp32 accum)
// Warp w owns rows w*16..w*16+15; two passes of 16 n8-tiles (128 cols each).
// Epilogue: +b1 on A half, fp16 pack, store to g_Ah/g_Bh.
// ---------------------------------------------------------------------------
__global__ void __launch_bounds__(256) node_mma(const float* __restrict__ z,
                                                const float* __restrict__ b1) {
    extern __shared__ char smem[];
    const int tid  = threadIdx.x;
    const int wid  = tid >> 5;
    const int lane = tid & 31;
    const int gr   = lane >> 2;   // group row 0..7
    const int cc   = lane & 3;    // thread-in-group 0..3
    const int nodeBase = blockIdx.x * 128;

    // b1 -> smem
    if (tid < 128) ((float*)(smem + SM_B1))[tid] = b1[tid];

    // W tiles: linear copy (already swizzled in gmem)
    {
        const uint4* sh = (const uint4*)g_Wh;
        const uint4* sl = (const uint4*)g_Wl;
        uint4* dh = (uint4*)(smem + SM_WH);
        uint4* dl = (uint4*)(smem + SM_WL);
        #pragma unroll
        for (int i = 0; i < 8; i++) {
            dh[tid + i * 256] = sh[tid + i * 256];
            dl[tid + i * 256] = sl[tid + i * 256];
        }
    }

    // z tile: 128 rows x 64 cols fp32 -> zh/zl fp16, swizzled
    {
        #pragma unroll
        for (int i = 0; i < 16; i++) {
            int p    = tid + i * 256;     // 0..4095 half2-slots
            int r    = p >> 5;            // row
            int kp   = p & 31;            // half2 col (k = 2*kp)
            int node = nodeBase + r;
            float2 zv = (node < N_NODES)
                      ? ((const float2*)z)[(size_t)node * 32 + kp]
                      : make_float2(0.f, 0.f);
            __half2 h = __floats2half2_rn(zv.x, zv.y);
            __half2 l = __floats2half2_rn(zv.x - __low2float(h),
                                          zv.y - __high2float(h));
            uint32_t off = (uint32_t)(r * 128 + ((4 * kp) ^ ((r & 7) << 4)));
            *(uint32_t*)(smem + SM_ZH + off) = *(const uint32_t*)&h;
            *(uint32_t*)(smem + SM_ZL + off) = *(const uint32_t*)&l;
        }
    }
    __syncthreads();

    // A fragments for this warp's 16-row slab (8 frags x 4 regs)
    const int rowlo = wid * 16 + gr;
    const int rowhi = rowlo + 8;
    const int sw    = gr << 4;   // (row & 7) == gr for both rowlo and rowhi
    uint32_t aH[4][4], aL[4][4];
    #pragma unroll
    for (int ks = 0; ks < 4; ks++) {
        int k0 = ks * 32 + 4 * cc;
        int oLo = k0 ^ sw, oHi = (k0 + 16) ^ sw;
        aH[ks][0] = *(const uint32_t*)(smem + SM_ZH + rowlo * 128 + oLo);
        aH[ks][1] = *(const uint32_t*)(smem + SM_ZH + rowhi * 128 + oLo);
        aH[ks][2] = *(const uint32_t*)(smem + SM_ZH + rowlo * 128 + oHi);
        aH[ks][3] = *(const uint32_t*)(smem + SM_ZH + rowhi * 128 + oHi);
        aL[ks][0] = *(const uint32_t*)(smem + SM_ZL + rowlo * 128 + oLo);
        aL[ks][1] = *(const uint32_t*)(smem + SM_ZL + rowhi * 128 + oLo);
        aL[ks][2] = *(const uint32_t*)(smem + SM_ZL + rowlo * 128 + oHi);
        aL[ks][3] = *(const uint32_t*)(smem + SM_ZL + rowhi * 128 + oHi);
    }

    const int node0 = nodeBase + rowlo;
    const int node1 = nodeBase + rowhi;
    const float* sB1 = (const float*)(smem + SM_B1);

    #pragma unroll
    for (int pass = 0; pass < 2; pass++) {
        float acc[16][4];
        #pragma unroll
        for (int nt = 0; nt < 16; nt++)
            #pragma unroll
            for (int q = 0; q < 4; q++) acc[nt][q] = 0.f;

        #pragma unroll
        for (int ks = 0; ks < 4; ks++) {
            int k0  = ks * 32 + 4 * cc;
            int oLo = k0 ^ sw, oHi = (k0 + 16) ^ sw;
            #pragma unroll
            for (int nt = 0; nt < 16; nt++) {
                int n = (pass * 16 + nt) * 8 + gr;   // n&7 == gr
                const char* bH = smem + SM_WH + n * 128;
                const char* bL = smem + SM_WL + n * 128;
                uint32_t h0 = *(const uint32_t*)(bH + oLo);
                uint32_t h1 = *(const uint32_t*)(bH + oHi);
                uint32_t l0 = *(const uint32_t*)(bL + oLo);
                uint32_t l1 = *(const uint32_t*)(bL + oHi);
                mma16816(acc[nt], aH[ks], h0, h1);
                mma16816(acc[nt], aH[ks], l0, l1);
                mma16816(acc[nt], aL[ks], h0, h1);
            }
        }

        // store this pass's 128 columns
        #pragma unroll
        for (int nt = 0; nt < 16; nt++) {
            int ntg = pass * 16 + nt;
            int col = ntg * 8 + 2 * cc;
            float add0 = 0.f, add1 = 0.f;
            __half* dstT;
            int c2;
            if (ntg < 16) { add0 = sB1[col]; add1 = sB1[col + 1]; dstT = g_Ah; c2 = col; }
            else          { dstT = g_Bh; c2 = col - 128; }
            __half2 d0 = __floats2half2_rn(acc[nt][0] + add0, acc[nt][1] + add1);
            __half2 d1 = __floats2half2_rn(acc[nt][2] + add0, acc[nt][3] + add1);
            if (node0 < N_NODES)
                *(uint32_t*)(dstT + (size_t)node0 * NH + c2) = *(const uint32_t*)&d0;
            if (node1 < N_NODES)
                *(uint32_t*)(dstT + (size_t)node1 * NH + c2) = *(const uint32_t*)&d1;
        }
    }
}

// ---------------------------------------------------------------------------
// Kernel 2: edge pass (R4, unchanged): persistent grid-stride,
// out[e] = W2 . relu(A[row]+B[col]) + b2.  8 lanes/edge, unroll-by-2.
// ---------------------------------------------------------------------------
#define EDGE_BLOCKS 1184

__global__ void edge_kernel(const int* __restrict__ row, const int* __restrict__ col,
                            const float* __restrict__ W2, const float* __restrict__ b2,
                            float* __restrict__ out) {
    const int lane = threadIdx.x & 31;
    const int warp = threadIdx.x >> 5;
    const int g    = lane >> 3;
    const int i    = lane & 7;

    const float4* W24 = (const float4*)W2;
    float4 w4[4];
    #pragma unroll
    for (int q = 0; q < 2; q++)
        #pragma unroll
        for (int h = 0; h < 2; h++)
            w4[q * 2 + h] = W24[(q * 8 + i) * 2 + h];
    const float bias = b2[0];

    const int warpGlobal = blockIdx.x * 8 + warp;
    const int nWarps     = EDGE_BLOCKS * 8;

    for (long e0 = (long)warpGlobal * 8; e0 < N_EDGES; e0 += (long)nWarps * 8) {
        const long eA = e0 + g;
        const long eB = e0 + 4 + g;

        const int rA = row[eA], cA = col[eA];
        const int rB = row[eB], cB = col[eB];

        const uint4* __restrict__ ArA = (const uint4*)(g_Ah + (size_t)rA * NH);
        const uint4* __restrict__ BcA = (const uint4*)(g_Bh + (size_t)cA * NH);
        const uint4* __restrict__ ArB = (const uint4*)(g_Ah + (size_t)rB * NH);
        const uint4* __restrict__ BcB = (const uint4*)(g_Bh + (size_t)cB * NH);

        uint4 avA[2], bvA[2], avB[2], bvB[2];
        #pragma unroll
        for (int q = 0; q < 2; q++) {
            avA[q] = ArA[q * 8 + i];  bvA[q] = BcA[q * 8 + i];
            avB[q] = ArB[q * 8 + i];  bvB[q] = BcB[q * 8 + i];
        }

        float sA = 0.f, sB = 0.f;
        #pragma unroll
        for (int q = 0; q < 2; q++) {
            const __half2* ahA = (const __half2*)&avA[q];
            const __half2* bhA = (const __half2*)&bvA[q];
            const __half2* ahB = (const __half2*)&avB[q];
            const __half2* bhB = (const __half2*)&bvB[q];
            const float* wq = (const float*)&w4[q * 2];
            #pragma unroll
            for (int t = 0; t < 4; t++) {
                float2 afA = __half22float2(ahA[t]);
                float2 bfA = __half22float2(bhA[t]);
                sA += wq[2 * t]     * fmaxf(afA.x + bfA.x, 0.f);
                sA += wq[2 * t + 1] * fmaxf(afA.y + bfA.y, 0.f);
                float2 afB = __half22float2(ahB[t]);
                float2 bfB = __half22float2(bhB[t]);
                sB += wq[2 * t]     * fmaxf(afB.x + bfB.x, 0.f);
                sB += wq[2 * t + 1] * fmaxf(afB.y + bfB.y, 0.f);
            }
        }

        sA += __shfl_xor_sync(0xffffffffu, sA, 1);
        sA += __shfl_xor_sync(0xffffffffu, sA, 2);
        sA += __shfl_xor_sync(0xffffffffu, sA, 4);
        sB += __shfl_xor_sync(0xffffffffu, sB, 1);
        sB += __shfl_xor_sync(0xffffffffu, sB, 2);
        sB += __shfl_xor_sync(0xffffffffu, sB, 4);

        if (i == 0) {
            out[eA] = sA + bias;
            out[eB] = sB + bias;
        }
    }
}

// ---------------------------------------------------------------------------
extern "C" void kernel_launch(void* const* d_in, const int* in_sizes, int n_in,
                              void* d_out, int out_size) {
    const float* z   = (const float*)d_in[0];
    const int*   row = (const int*)  d_in[1];
    const int*   col = (const int*)  d_in[2];
    const float* W1  = (const float*)d_in[3];
    const float* b1  = (const float*)d_in[4];
    const float* W2  = (const float*)d_in[5];
    const float* b2  = (const float*)d_in[6];
    float* out = (float*)d_out;

    cudaFuncSetAttribute(node_mma, cudaFuncAttributeMaxDynamicSharedMemorySize, SM_TOT);

    build_wt<<<64, 256>>>(W1);
    node_mma<<<(N_NODES + 127) / 128, 256, SM_TOT>>>(z, b1);      // 782 blocks
    edge_kernel<<<EDGE_BLOCKS, 256>>>(row, col, W2, b2, out);     // persistent
}